// round 17
// baseline (speedup 1.0000x reference)
#include <cuda_runtime.h>
#include <cuda_fp16.h>
#include <cstdint>

#define T_TOK 16384
#define DM    512
#define DFF   2048
#define HN    8
#define SQ    512
#define BATCH 32
#define NLAYER 6
#define EPSBN 1e-5f
typedef __half h16;
typedef long long ll;

// ---------------- asm helpers (plain sm_80+ PTX) ----------------
__device__ __forceinline__ uint32_t smem_u32(const void* p) {
  uint32_t a;
  asm("{ .reg .u64 t; cvta.to.shared.u64 t, %1; cvt.u32.u64 %0, t; }" : "=r"(a) : "l"(p));
  return a;
}
__device__ __forceinline__ void ldsm4(uint32_t* r, uint32_t a) {
  asm volatile("ldmatrix.sync.aligned.m8n8.x4.shared.b16 {%0,%1,%2,%3}, [%4];"
               : "=r"(r[0]), "=r"(r[1]), "=r"(r[2]), "=r"(r[3]) : "r"(a));
}
__device__ __forceinline__ void ldsm4t(uint32_t* r, uint32_t a) {
  asm volatile("ldmatrix.sync.aligned.m8n8.x4.trans.shared.b16 {%0,%1,%2,%3}, [%4];"
               : "=r"(r[0]), "=r"(r[1]), "=r"(r[2]), "=r"(r[3]) : "r"(a));
}
__device__ __forceinline__ void mma16816(float* c, const uint32_t* a, const uint32_t* b) {
  asm volatile(
      "mma.sync.aligned.m16n8k16.row.col.f32.f16.f16.f32 "
      "{%0,%1,%2,%3}, {%4,%5,%6,%7}, {%8,%9}, {%0,%1,%2,%3};"
      : "+f"(c[0]), "+f"(c[1]), "+f"(c[2]), "+f"(c[3])
      : "r"(a[0]), "r"(a[1]), "r"(a[2]), "r"(a[3]), "r"(b[0]), "r"(b[1]));
}
__device__ __forceinline__ void cpa16(uint32_t s, const void* g) {
  asm volatile("cp.async.cg.shared.global [%0], [%1], 16;" :: "r"(s), "l"(g));
}
__device__ __forceinline__ uint32_t pack2(h16 a, h16 b) {
  return (uint32_t)__half_as_ushort(a) | ((uint32_t)__half_as_ushort(b) << 16);
}

// ---------------- Static scratch ----------------
__device__ float g_X[(size_t)T_TOK * DM];
__device__ float g_Y[(size_t)T_TOK * DM];
__device__ h16 g_Xh[(size_t)T_TOK * DM];
__device__ h16 g_QKVh[(size_t)T_TOK * 1536];
__device__ h16 g_ATTh[(size_t)T_TOK * DM];
__device__ h16 g_Fh[(size_t)T_TOK * DFF];
__device__ h16 g_WQKVTh[(size_t)NLAYER * 1536 * 512];
__device__ h16 g_WOTh[(size_t)NLAYER * 512 * 512];
__device__ h16 g_W1Th[(size_t)NLAYER * 2048 * 512];
__device__ h16 g_W2Th[(size_t)NLAYER * 512 * 2048];
__device__ float g_partS[256 * DM], g_partQ[256 * DM], g_nrm[2 * DM];

// ------- mma.sync fp16 GEMM: C = alpha*Ah@Bh^T (+bias)(+res)(relu) -------
template <int BN, int OUTM, bool BIAS, bool RELU, bool RES>
__global__ void __launch_bounds__(256)
mm_gemm(const h16* __restrict__ Ah, const h16* __restrict__ Bh,
        float* __restrict__ C, h16* __restrict__ Ch,
        const float* __restrict__ Res, const float* __restrict__ bias,
        int K, int lda, int ldb, int ldc, float alpha, int zInner,
        ll sAo, ll sAi, ll sBo, ll sBi, ll sCo, ll sCi) {
  constexpr int WRM = (BN == 128) ? 2 : 4;
  constexpr int WRN = 8 / WRM;
  constexpr int WTM = 128 / WRM;
  constexpr int WTN = BN / WRN;
  constexpr int MT = WTM / 16;
  constexpr int NT = WTN / 8;
  constexpr int AB = 128 * 80;
  constexpr int BB = BN * 80;
  constexpr int SB = AB + BB;

  extern __shared__ char dynsm[];
  const uint32_t sb = smem_u32(dynsm);

  const int tid = threadIdx.x, wid = tid >> 5, lane = tid & 31;
  const int wm = wid / WRN, wn = wid % WRN;
  const int zo = blockIdx.z / zInner, zi = blockIdx.z % zInner;

  const h16* A_h = Ah + zo * sAo + zi * sAi + (ll)blockIdx.x * 128 * lda;
  const h16* B_h = Bh + zo * sBo + zi * sBi + (ll)blockIdx.y * BN * ldb;
  const ll coff = zo * sCo + zi * sCi + (ll)blockIdx.x * 128 * ldc + (ll)blockIdx.y * BN;

  float acc[MT][NT][4];
#pragma unroll
  for (int i = 0; i < MT; i++)
#pragma unroll
    for (int j = 0; j < NT; j++)
#pragma unroll
      for (int e = 0; e < 4; e++) acc[i][j][e] = 0.f;

  auto load_stage = [&](int kt, int s) {
    const int k0 = kt * 32;
    const uint32_t s0 = sb + s * SB;
#pragma unroll 2
    for (int i = tid; i < 128 * 4; i += 256) {
      const int r = i >> 2, c = i & 3;
      cpa16(s0 + (uint32_t)(r * 80 + c * 16), A_h + (ll)r * lda + k0 + c * 8);
    }
#pragma unroll
    for (int i = tid; i < BN * 4; i += 256) {
      const int r = i >> 2, c = i & 3;
      cpa16(s0 + AB + (uint32_t)(r * 80 + c * 16), B_h + (ll)r * ldb + k0 + c * 8);
    }
  };

  const int KT = K >> 5;
  load_stage(0, 0);
  asm volatile("cp.async.commit_group;");

  const uint32_t arow = (uint32_t)(lane & 15);
  const uint32_t acol = (uint32_t)((lane >> 4) * 16);
  const uint32_t brow = (uint32_t)((lane & 7) + ((lane >> 4) << 3));
  const uint32_t bcol = (uint32_t)(((lane >> 3) & 1) * 16);

  for (int kt = 0; kt < KT; kt++) {
    if (kt + 1 < KT) {
      load_stage(kt + 1, (kt + 1) & 1);
      asm volatile("cp.async.commit_group;");
      asm volatile("cp.async.wait_group 1;");
    } else {
      asm volatile("cp.async.wait_group 0;");
    }
    __syncthreads();

    const uint32_t abase = sb + (kt & 1) * SB;
    const uint32_t bbase = abase + AB;
#pragma unroll
    for (int ks = 0; ks < 2; ks++) {
      uint32_t aH[MT][4], bH[NT][2];
#pragma unroll
      for (int mt = 0; mt < MT; mt++) {
        ldsm4(aH[mt], abase + (wm * WTM + mt * 16 + arow) * 80 + ks * 32 + acol);
      }
#pragma unroll
      for (int p = 0; p < NT / 2; p++) {
        uint32_t t[4];
        ldsm4(t, bbase + (wn * WTN + p * 16 + brow) * 80 + ks * 32 + bcol);
        bH[2 * p][0] = t[0]; bH[2 * p][1] = t[1];
        bH[2 * p + 1][0] = t[2]; bH[2 * p + 1][1] = t[3];
      }
#pragma unroll
      for (int mt = 0; mt < MT; mt++)
#pragma unroll
        for (int nt = 0; nt < NT; nt++)
          mma16816(acc[mt][nt], aH[mt], bH[nt]);
    }
    __syncthreads();
  }

#pragma unroll
  for (int mt = 0; mt < MT; mt++) {
#pragma unroll
    for (int nt = 0; nt < NT; nt++) {
      const int r0 = wm * WTM + mt * 16 + (lane >> 2);
      const int cc = wn * WTN + nt * 8 + (lane & 3) * 2;
      float v0 = acc[mt][nt][0] * alpha, v1 = acc[mt][nt][1] * alpha;
      float v2 = acc[mt][nt][2] * alpha, v3 = acc[mt][nt][3] * alpha;
      if (BIAS) {
        const float b0v = bias[(ll)blockIdx.y * BN + cc];
        const float b1v = bias[(ll)blockIdx.y * BN + cc + 1];
        v0 += b0v; v2 += b0v; v1 += b1v; v3 += b1v;
      }
#pragma unroll
      for (int half = 0; half < 2; half++) {
        const int r = r0 + half * 8;
        float x0 = half ? v2 : v0, x1 = half ? v3 : v1;
        const ll go = coff + (ll)r * ldc + cc;
        if (RES) {
          const float2 rr = *reinterpret_cast<const float2*>(Res + go);
          x0 += rr.x; x1 += rr.y;
        }
        if (RELU) { x0 = fmaxf(x0, 0.f); x1 = fmaxf(x1, 0.f); }
        if (OUTM == 0) {
          *reinterpret_cast<float2*>(C + go) = make_float2(x0, x1);
        } else {
          *reinterpret_cast<uint32_t*>(Ch + go) =
              pack2(__float2half_rn(x0), __float2half_rn(x1));
        }
      }
    }
  }
}

// ------- fully fused attention: ATTh = softmax(Q@K^T/8) @ V -------
// grid (16, HN*BATCH): CTA = 32 query rows of one (h,b). 8 warps x 64 keys.
// smem: K 2x40960, V 2x40960, Q 2x2560, red 2x1024. O partials reuse K area.
#define FA_K0 0
#define FA_K1 40960
#define FA_V0 81920
#define FA_V1 122880
#define FA_Q0 163840
#define FA_Q1 166400
#define FA_RMAX 168960
#define FA_RSUM 169984
#define FA_SMEM 171008
__global__ void __launch_bounds__(256)
attn_k(const h16* __restrict__ QKV, h16* __restrict__ ATTh) {
  extern __shared__ char dynsm[];
  const uint32_t sb = smem_u32(dynsm);
  float* redm = (float*)(dynsm + FA_RMAX);
  float* reds = (float*)(dynsm + FA_RSUM);

  const int tid = threadIdx.x, wid = tid >> 5, lane = tid & 31;
  const int by = blockIdx.y;            // h*32 + b
  const int h = by >> 5, b = by & 31;
  const int q0 = blockIdx.x * 32;

  // load K [512 x 64] and V [512 x 64] into two 32-col planes each (80B rows)
  const h16* Kbase = QKV + (ll)b * 512 * 1536 + 512 + h * 64;
  const h16* Vbase = QKV + (ll)b * 512 * 1536 + 1024 + h * 64;
#pragma unroll
  for (int i = tid; i < 512 * 8; i += 256) {
    const int kk = i >> 3, ks = (i >> 2) & 1, c = i & 3;
    const uint32_t so = (uint32_t)(kk * 80 + c * 16);
    cpa16(sb + (ks ? FA_K1 : FA_K0) + so, Kbase + (ll)kk * 1536 + ks * 32 + c * 8);
    cpa16(sb + (ks ? FA_V1 : FA_V0) + so, Vbase + (ll)kk * 1536 + ks * 32 + c * 8);
  }
  const h16* Qbase = QKV + (ll)(b * 512 + q0) * 1536 + h * 64;
#pragma unroll
  for (int i = tid; i < 32 * 8; i += 256) {
    const int r = i >> 3, ks = (i >> 2) & 1, c = i & 3;
    cpa16(sb + (ks ? FA_Q1 : FA_Q0) + (uint32_t)(r * 80 + c * 16),
          Qbase + (ll)r * 1536 + ks * 32 + c * 8);
  }
  asm volatile("cp.async.commit_group;");
  asm volatile("cp.async.wait_group 0;");
  __syncthreads();

  const uint32_t arow = (uint32_t)(lane & 15);
  const uint32_t acol = (uint32_t)((lane >> 4) * 16);
  const uint32_t brow = (uint32_t)((lane & 7) + ((lane >> 4) << 3));
  const uint32_t bcol = (uint32_t)(((lane >> 3) & 1) * 16);

  float acc[2][8][4];
#pragma unroll
  for (int i = 0; i < 2; i++)
#pragma unroll
    for (int j = 0; j < 8; j++)
#pragma unroll
      for (int e = 0; e < 4; e++) acc[i][j][e] = 0.f;

  // ---- scores: Q @ K^T ----
#pragma unroll
  for (int pl = 0; pl < 2; pl++) {
    const uint32_t qb = sb + (pl ? FA_Q1 : FA_Q0);
    const uint32_t kb = sb + (pl ? FA_K1 : FA_K0);
#pragma unroll
    for (int ks = 0; ks < 2; ks++) {
      uint32_t aH[2][4], bH[8][2];
#pragma unroll
      for (int mt = 0; mt < 2; mt++)
        ldsm4(aH[mt], qb + (mt * 16 + arow) * 80 + ks * 32 + acol);
#pragma unroll
      for (int p = 0; p < 4; p++) {
        uint32_t t[4];
        ldsm4(t, kb + (wid * 64 + p * 16 + brow) * 80 + ks * 32 + bcol);
        bH[2 * p][0] = t[0]; bH[2 * p][1] = t[1];
        bH[2 * p + 1][0] = t[2]; bH[2 * p + 1][1] = t[3];
      }
#pragma unroll
      for (int mt = 0; mt < 2; mt++)
#pragma unroll
        for (int nt = 0; nt < 8; nt++)
          mma16816(acc[mt][nt], aH[mt], bH[nt]);
    }
  }

#pragma unroll
  for (int i = 0; i < 2; i++)
#pragma unroll
    for (int j = 0; j < 8; j++)
#pragma unroll
      for (int e = 0; e < 4; e++) acc[i][j][e] *= 0.125f;

  // ---- softmax: row max / sum across 8 warps via smem ----
  float wmax[2][2];
#pragma unroll
  for (int mt = 0; mt < 2; mt++)
#pragma unroll
    for (int hf = 0; hf < 2; hf++) {
      float m = -1e30f;
#pragma unroll
      for (int nt = 0; nt < 8; nt++)
        m = fmaxf(m, fmaxf(acc[mt][nt][2 * hf], acc[mt][nt][2 * hf + 1]));
      m = fmaxf(m, __shfl_xor_sync(0xffffffffu, m, 1));
      m = fmaxf(m, __shfl_xor_sync(0xffffffffu, m, 2));
      wmax[mt][hf] = m;
    }
  if ((lane & 3) == 0) {
#pragma unroll
    for (int mt = 0; mt < 2; mt++)
#pragma unroll
      for (int hf = 0; hf < 2; hf++)
        redm[(mt * 16 + (lane >> 2) + hf * 8) * 8 + wid] = wmax[mt][hf];
  }
  __syncthreads();
  float gmax[2][2];
#pragma unroll
  for (int mt = 0; mt < 2; mt++)
#pragma unroll
    for (int hf = 0; hf < 2; hf++) {
      const int row = mt * 16 + (lane >> 2) + hf * 8;
      float m = redm[row * 8 + 0];
#pragma unroll
      for (int w = 1; w < 8; w++) m = fmaxf(m, redm[row * 8 + w]);
      gmax[mt][hf] = m;
    }

  float wsum[2][2];
#pragma unroll
  for (int mt = 0; mt < 2; mt++)
#pragma unroll
    for (int hf = 0; hf < 2; hf++) {
      float s = 0.f;
#pragma unroll
      for (int nt = 0; nt < 8; nt++) {
        float e0 = __expf(acc[mt][nt][2 * hf] - gmax[mt][hf]);
        float e1 = __expf(acc[mt][nt][2 * hf + 1] - gmax[mt][hf]);
        acc[mt][nt][2 * hf] = e0;
        acc[mt][nt][2 * hf + 1] = e1;
        s += e0 + e1;
      }
      s += __shfl_xor_sync(0xffffffffu, s, 1);
      s += __shfl_xor_sync(0xffffffffu, s, 2);
      wsum[mt][hf] = s;
    }
  if ((lane & 3) == 0) {
#pragma unroll
    for (int mt = 0; mt < 2; mt++)
#pragma unroll
      for (int hf = 0; hf < 2; hf++)
        reds[(mt * 16 + (lane >> 2) + hf * 8) * 8 + wid] = wsum[mt][hf];
  }
  __syncthreads();

  float inv[2][2];
#pragma unroll
  for (int mt = 0; mt < 2; mt++)
#pragma unroll
    for (int hf = 0; hf < 2; hf++) {
      const int row = mt * 16 + (lane >> 2) + hf * 8;
      float s = 0.f;
#pragma unroll
      for (int w = 0; w < 8; w++) s += reds[row * 8 + w];
      inv[mt][hf] = 1.f / s;
    }

  // ---- convert P accumulators into fp16 A-fragments (in registers) ----
  // A m16k16 fragment for k-chunk kc = acc n-blocks {2kc, 2kc+1}:
  //   ra0=(r,k0-7) ra1=(r+8,k0-7) ra2=(r,k8-15) ra3=(r+8,k8-15)
  uint32_t ra[2][4][4];
#pragma unroll
  for (int mt = 0; mt < 2; mt++)
#pragma unroll
    for (int kc = 0; kc < 4; kc++) {
      ra[mt][kc][0] = pack2(__float2half_rn(acc[mt][2 * kc][0] * inv[mt][0]),
                            __float2half_rn(acc[mt][2 * kc][1] * inv[mt][0]));
      ra[mt][kc][1] = pack2(__float2half_rn(acc[mt][2 * kc][2] * inv[mt][1]),
                            __float2half_rn(acc[mt][2 * kc][3] * inv[mt][1]));
      ra[mt][kc][2] = pack2(__float2half_rn(acc[mt][2 * kc + 1][0] * inv[mt][0]),
                            __float2half_rn(acc[mt][2 * kc + 1][1] * inv[mt][0]));
      ra[mt][kc][3] = pack2(__float2half_rn(acc[mt][2 * kc + 1][2] * inv[mt][1]),
                            __float2half_rn(acc[mt][2 * kc + 1][3] * inv[mt][1]));
    }

  // ---- O = P @ V : V fragments via ldmatrix.trans from [keys][vdim] smem ----
  float oac[2][8][4];
#pragma unroll
  for (int i = 0; i < 2; i++)
#pragma unroll
    for (int j = 0; j < 8; j++)
#pragma unroll
      for (int e = 0; e < 4; e++) oac[i][j][e] = 0.f;

#pragma unroll
  for (int kc = 0; kc < 4; kc++) {
    uint32_t vf[4][4];
#pragma unroll
    for (int nc = 0; nc < 4; nc++) {
      const uint32_t va = sb + (nc < 2 ? FA_V0 : FA_V1) +
          (uint32_t)((wid * 64 + kc * 16 + (lane & 7) + ((lane >> 4) << 3)) * 80 +
                     (nc & 1) * 32 + ((lane >> 3) & 1) * 16);
      ldsm4t(vf[nc], va);
    }
#pragma unroll
    for (int mt = 0; mt < 2; mt++)
#pragma unroll
      for (int nc = 0; nc < 4; nc++) {
        uint32_t b0[2] = {vf[nc][0], vf[nc][2]};
        uint32_t b1[2] = {vf[nc][1], vf[nc][3]};
        mma16816(oac[mt][2 * nc], ra[mt][kc], b0);
        mma16816(oac[mt][2 * nc + 1], ra[mt][kc], b1);
      }
  }

  // ---- cross-warp reduction of O partials (reuse K smem area) ----
  float* op = (float*)dynsm + wid * 2048;   // [32 rows][64 vdim]
#pragma unroll
  for (int mt = 0; mt < 2; mt++)
#pragma unroll
    for (int nt = 0; nt < 8; nt++) {
      const int r = mt * 16 + (lane >> 2);
      const int v = nt * 8 + (lane & 3) * 2;
      op[r * 64 + v] = oac[mt][nt][0];
      op[r * 64 + v + 1] = oac[mt][nt][1];
      op[(r + 8) * 64 + v] = oac[mt][nt][2];
      op[(r + 8) * 64 + v + 1] = oac[mt][nt][3];
    }
  __syncthreads();

  const int row = tid >> 3, v0 = (tid & 7) * 8;
  float s[8];
#pragma unroll
  for (int j = 0; j < 8; j++) s[j] = 0.f;
#pragma unroll
  for (int w = 0; w < 8; w++) {
    const float* p = (float*)dynsm + w * 2048 + row * 64 + v0;
#pragma unroll
    for (int j = 0; j < 8; j++) s[j] += p[j];
  }
  uint4 o;
  o.x = pack2(__float2half_rn(s[0]), __float2half_rn(s[1]));
  o.y = pack2(__float2half_rn(s[2]), __float2half_rn(s[3]));
  o.z = pack2(__float2half_rn(s[4]), __float2half_rn(s[5]));
  o.w = pack2(__float2half_rn(s[6]), __float2half_rn(s[7]));
  *reinterpret_cast<uint4*>(ATTh + (ll)(b * 512 + q0 + row) * 512 + h * 64 + v0) = o;
}

// -------- transpose + round: fp32 [R,C] -> fp16 hi [C,R]; batched 2-level z ------
__global__ void tsplit_k(const float* __restrict__ in, h16* __restrict__ oh,
                         int R, int C, int zInner,
                         ll sIno, ll sIni, ll sOuto, ll sOuti) {
  __shared__ float t[32][33];
  const int zo = blockIdx.z / zInner, zi = blockIdx.z % zInner;
  const float* I = in + zo * sIno + zi * sIni;
  h16* O = oh + zo * sOuto + zi * sOuti;
  int c0 = blockIdx.x * 32, r0 = blockIdx.y * 32;
#pragma unroll
  for (int i = 0; i < 4; i++)
    t[threadIdx.y + i * 8][threadIdx.x] =
        I[(ll)(r0 + threadIdx.y + i * 8) * C + c0 + threadIdx.x];
  __syncthreads();
#pragma unroll
  for (int i = 0; i < 4; i++) {
    int c = c0 + threadIdx.y + i * 8;
    O[(ll)c * R + r0 + threadIdx.x] = __float2half_rn(t[threadIdx.x][threadIdx.y + i * 8]);
  }
}

// ---------------- elementwise ----------------
__global__ void embed_k(const int* __restrict__ tok, const float* __restrict__ emb,
                        float* __restrict__ X, h16* __restrict__ Xh) {
  int t = blockIdx.x, c4 = threadIdx.x;
  float4 v = reinterpret_cast<const float4*>(emb + (ll)tok[t] * DM)[c4];
  v.x *= 8.f; v.y *= 8.f; v.z *= 8.f; v.w *= 8.f;
  ll go = (ll)t * DM + c4 * 4;
  *reinterpret_cast<float4*>(X + go) = v;
  *reinterpret_cast<uint2*>(Xh + go) = make_uint2(
      pack2(__float2half_rn(v.x), __float2half_rn(v.y)),
      pack2(__float2half_rn(v.z), __float2half_rn(v.w)));
}

__global__ void bn_part_k(const float* __restrict__ Y, float* __restrict__ pS,
                          float* __restrict__ pQ) {
  int c = threadIdx.x, p = blockIdx.x;
  const float* base = Y + (ll)p * 64 * DM + c;
  float s = 0.f, q = 0.f;
#pragma unroll 8
  for (int r = 0; r < 64; r++) { float v = base[(ll)r * DM]; s += v; q += v * v; }
  pS[p * DM + c] = s; pQ[p * DM + c] = q;
}
__global__ void bn_finish_k(const float* __restrict__ pS, const float* __restrict__ pQ,
                            const float* __restrict__ g, const float* __restrict__ be,
                            float* __restrict__ nrm) {
  int c = threadIdx.x;
  float s = 0.f, q = 0.f;
  for (int p = 0; p < 256; p++) { s += pS[p * DM + c]; q += pQ[p * DM + c]; }
  const float invN = 1.f / (float)T_TOK;
  float mean = s * invN, var = q * invN - mean * mean;
  float a = g[c] * rsqrtf(var + EPSBN);
  nrm[c] = a; nrm[DM + c] = be[c] - mean * a;
}
__global__ void bn_apply_k(const float* __restrict__ Y, const float* __restrict__ nrm,
                           float* __restrict__ X, h16* __restrict__ Xh) {
  ll idx = ((ll)blockIdx.x * blockDim.x + threadIdx.x) * 4;
  int c = (int)(idx & (DM - 1));
  float4 v = *reinterpret_cast<const float4*>(Y + idx);
  float4 o;
  o.x = v.x * nrm[c] + nrm[DM + c];
  o.y = v.y * nrm[c + 1] + nrm[DM + c + 1];
  o.z = v.z * nrm[c + 2] + nrm[DM + c + 2];
  o.w = v.w * nrm[c + 3] + nrm[DM + c + 3];
  *reinterpret_cast<float4*>(X + idx) = o;
  *reinterpret_cast<uint2*>(Xh + idx) = make_uint2(
      pack2(__float2half_rn(o.x), __float2half_rn(o.y)),
      pack2(__float2half_rn(o.z), __float2half_rn(o.w)));
}

// ---------------- host ----------------
#define GETP(var, sym) void* p_##var; cudaGetSymbolAddress(&p_##var, sym)
extern "C" void kernel_launch(void* const* d_in, const int* in_sizes, int n_in,
                              void* d_out, int out_size) {
  (void)in_sizes; (void)n_in; (void)out_size;
  const int* tokens = (const int*)d_in[0];
  const float* emb = (const float*)d_in[1];
  const float *WQ = (const float*)d_in[2], *WK = (const float*)d_in[3];
  const float *WV = (const float*)d_in[4], *WO = (const float*)d_in[5];
  const float *g1 = (const float*)d_in[6], *be1 = (const float*)d_in[7];
  const float *W1 = (const float*)d_in[8], *b1 = (const float*)d_in[9];
  const float *W2 = (const float*)d_in[10], *b2 = (const float*)d_in[11];
  const float *g2 = (const float*)d_in[12], *be2 = (const float*)d_in[13];
  float* out = (float*)d_out;

  GETP(X, g_X); GETP(Y, g_Y);
  GETP(Xh, g_Xh); GETP(QKVh, g_QKVh);
  GETP(ATTh, g_ATTh); GETP(Fh, g_Fh);
  GETP(WQKVTh, g_WQKVTh); GETP(WOTh, g_WOTh);
  GETP(W1Th, g_W1Th); GETP(W2Th, g_W2Th);
  GETP(pS, g_partS); GETP(pQ, g_partQ); GETP(nrm, g_nrm);
  float *X = (float*)p_X, *Y = (float*)p_Y;
  h16 *Xh = (h16*)p_Xh, *QKVh = (h16*)p_QKVh;
  h16 *ATTh = (h16*)p_ATTh, *Fh = (h16*)p_Fh;
  h16 *WQKVTa = (h16*)p_WQKVTh, *WOTa = (h16*)p_WOTh;
  h16 *W1Ta = (h16*)p_W1Th, *W2Ta = (h16*)p_W2Th;
  float *partS = (float*)p_pS, *partQ = (float*)p_pQ, *nrm = (float*)p_nrm;

  const int SM_S128 = 2 * (128 * 80 + 128 * 80);  // 40960
  cudaFuncSetAttribute(mm_gemm<128, 1, false, false, false>, cudaFuncAttributeMaxDynamicSharedMemorySize, SM_S128);
  cudaFuncSetAttribute(mm_gemm<128, 0, false, false, true>,  cudaFuncAttributeMaxDynamicSharedMemorySize, SM_S128);
  cudaFuncSetAttribute(mm_gemm<128, 1, true, true, false>,   cudaFuncAttributeMaxDynamicSharedMemorySize, SM_S128);
  cudaFuncSetAttribute(mm_gemm<128, 0, true, false, true>,   cudaFuncAttributeMaxDynamicSharedMemorySize, SM_S128);
  cudaFuncSetAttribute(attn_k, cudaFuncAttributeMaxDynamicSharedMemorySize, FA_SMEM);

  dim3 tb32(32, 8);

  embed_k<<<T_TOK, 128>>>(tokens, emb, X, Xh);

  // ---- batched weight prep for ALL layers ----
  tsplit_k<<<dim3(2, 16, NLAYER * HN), tb32>>>(WQ, WQKVTa, 512, 64, HN,
      (ll)HN * 512 * 64, (ll)512 * 64, (ll)1536 * 512, (ll)64 * 512);
  tsplit_k<<<dim3(2, 16, NLAYER * HN), tb32>>>(WK, WQKVTa + 512 * 512, 512, 64, HN,
      (ll)HN * 512 * 64, (ll)512 * 64, (ll)1536 * 512, (ll)64 * 512);
  tsplit_k<<<dim3(2, 16, NLAYER * HN), tb32>>>(WV, WQKVTa + 1024 * 512, 512, 64, HN,
      (ll)HN * 512 * 64, (ll)512 * 64, (ll)1536 * 512, (ll)64 * 512);
  tsplit_k<<<dim3(16, 16, NLAYER), tb32>>>(WO, WOTa, 512, 512, 1,
      (ll)512 * 512, 0, (ll)512 * 512, 0);
  tsplit_k<<<dim3(64, 16, NLAYER), tb32>>>(W1, W1Ta, 512, 2048, 1,
      (ll)512 * 2048, 0, (ll)2048 * 512, 0);
  tsplit_k<<<dim3(16, 64, NLAYER), tb32>>>(W2, W2Ta, 2048, 512, 1,
      (ll)2048 * 512, 0, (ll)512 * 2048, 0);

  for (int i = 0; i < NLAYER; i++) {
    const h16* WQKVT = WQKVTa + (ll)i * 1536 * 512;
    const h16* WOT = WOTa + (ll)i * 512 * 512;
    const h16* W1T = W1Ta + (ll)i * 2048 * 512;
    const h16* W2T = W2Ta + (ll)i * 512 * 2048;

    // QKV: [T,512] @ [1536,512]^T -> QKVh
    mm_gemm<128, 1, false, false, false><<<dim3(128, 12, 1), 256, SM_S128>>>(
        Xh, WQKVT, nullptr, QKVh, nullptr, nullptr,
        512, 512, 512, 1536, 1.f, 1, 0, 0, 0, 0, 0, 0);

    // fully fused attention -> ATTh
    attn_k<<<dim3(16, HN * BATCH), 256, FA_SMEM>>>(QKVh, ATTh);

    // O-proj + residual -> Y fp32
    mm_gemm<128, 0, false, false, true><<<dim3(128, 4, 1), 256, SM_S128>>>(
        ATTh, WOT, Y, nullptr, X, nullptr,
        512, 512, 512, 512, 1.f, 1, 0, 0, 0, 0, 0, 0);

    bn_part_k<<<256, DM>>>(Y, partS, partQ);
    bn_finish_k<<<1, DM>>>(partS, partQ, g1 + (ll)i * DM, be1 + (ll)i * DM, nrm);
    bn_apply_k<<<T_TOK * DM / 1024, 256>>>(Y, nrm, X, Xh);

    // FF1: relu(X@W1+b1) -> Fh
    mm_gemm<128, 1, true, true, false><<<dim3(128, 16, 1), 256, SM_S128>>>(
        Xh, W1T, nullptr, Fh, nullptr, b1 + (ll)i * DFF,
        512, 512, 512, 2048, 1.f, 1, 0, 0, 0, 0, 0, 0);

    // FF2 + bias + residual -> Y fp32
    mm_gemm<128, 0, true, false, true><<<dim3(128, 4, 1), 256, SM_S128>>>(
        Fh, W2T, Y, nullptr, X, b2 + (ll)i * DM,
        2048, 2048, 2048, 512, 1.f, 1, 0, 0, 0, 0, 0, 0);

    bn_part_k<<<256, DM>>>(Y, partS, partQ);
    bn_finish_k<<<1, DM>>>(partS, partQ, g2 + (ll)i * DM, be2 + (ll)i * DM, nrm);
    bn_apply_k<<<T_TOK * DM / 1024, 256>>>(Y, nrm, (i == NLAYER - 1) ? out : X, Xh);
  }
}